// round 4
// baseline (speedup 1.0000x reference)
#include <cuda_runtime.h>
#include <math.h>

#define NPTS   4096
#define NB     16
#define NARR   32           // 16 batches x 2 directions
#define D      3
#define NEL    (NPTS * D)   // 12288 residual elements per array
#define NHALF  2            // target-dimension split
#define THALF  (NPTS / NHALF)
#define TILE   1024         // targets per smem tile (16KB)
#define NPAIR  (TILE / 2)
#define CPAIRS 16           // pairs per chunk
#define CT     (2 * CPAIRS) // 32 targets per chunk

// Scratch (device globals only; no allocation allowed)
__device__ float4 g_part[(size_t)NARR * NHALF * NPTS]; // {score, rx, ry, rz}
__device__ float  g_resid[(size_t)NARR * NEL];
__device__ float  g_sigma[NARR];

// ---------------------------------------------------------------------------
// f32x2 packed helpers (sm_103a). Lane math bitwise == scalar fma.rn.f32.
// ---------------------------------------------------------------------------
__device__ __forceinline__ unsigned long long ffma2_u(
    unsigned long long a, unsigned long long b, unsigned long long c)
{
    unsigned long long d;
    asm("fma.rn.f32x2 %0, %1, %2, %3;" : "=l"(d) : "l"(a), "l"(b), "l"(c));
    return d;
}
__device__ __forceinline__ unsigned long long pack2(float lo, float hi)
{
    unsigned long long r;
    asm("mov.b64 %0, {%1, %2};" : "=l"(r) : "f"(lo), "f"(hi));
    return r;
}
__device__ __forceinline__ void unpack2(unsigned long long v, float& lo, float& hi)
{
    asm("mov.b64 {%0, %1}, %2;" : "=f"(lo), "=f"(hi) : "l"(v));
}

// Shared between tile-fill and rescan so the contraction is identical.
__device__ __forceinline__ float neg_half_norm(float x, float y, float z)
{
    return -0.5f * fmaf(x, x, fmaf(y, y, z * z));
}

// ---------------------------------------------------------------------------
// Kernel A: brute-force NN over a HALF of the target set.
// Inner loop: pure running max, operands flow LDS.128 -> f32x2 with no MOVs.
// Winning 32-target chunk rescanned from global to recover index/residual.
// grid = (16 query-chunks, NHALF, NARR), block = 128.
// ---------------------------------------------------------------------------
__global__ __launch_bounds__(128) void nn_part_kernel(
    const float* __restrict__ x, const float* __restrict__ y)
{
    const int arr   = blockIdx.z;          // 0..31
    const int half  = blockIdx.y;          // 0..1
    const int batch = arr >> 1;
    const int dir   = arr & 1;
    const float* Qp = (dir == 0) ? (x + (size_t)batch * NPTS * D)
                                 : (y + (size_t)batch * NPTS * D);
    const float* Tp = (dir == 0) ? (y + (size_t)batch * NPTS * D)
                                 : (x + (size_t)batch * NPTS * D);

    // pair-interleaved: sxy[p]={x0,x1,y0,y1}, szw[p]={z0,z1,-n0/2,-n1/2}
    __shared__ float4 sxy[NPAIR];
    __shared__ float4 szw[NPAIR];

    const int tid = threadIdx.x;           // 128 threads
    const int QN  = 2;
    const int qbase = blockIdx.x * (128 * QN);
    const int tbase = half * THALF;
    const float NEG_INF = __int_as_float(0xff800000);

    unsigned long long axx[QN], ayy[QN], azz[QN];
    float ax[QN], ay[QN], az[QN];
    float gbest[QN];
    int   gchunk[QN];
#pragma unroll
    for (int q = 0; q < QN; q++) {
        int qi = qbase + tid + q * 128;
        ax[q] = Qp[3 * qi + 0];
        ay[q] = Qp[3 * qi + 1];
        az[q] = Qp[3 * qi + 2];
        axx[q] = pack2(ax[q], ax[q]);
        ayy[q] = pack2(ay[q], ay[q]);
        azz[q] = pack2(az[q], az[q]);
        gbest[q]  = NEG_INF;
        gchunk[q] = tbase;
    }

    for (int t = tbase; t < tbase + THALF; t += TILE) {
        __syncthreads();
        for (int p = tid; p < NPAIR; p += 128) {
            const float* p0 = Tp + 3 * (size_t)(t + 2 * p);
            float x0 = p0[0], y0 = p0[1], z0 = p0[2];
            float x1 = p0[3], y1 = p0[4], z1 = p0[5];
            sxy[p] = make_float4(x0, x1, y0, y1);
            szw[p] = make_float4(z0, z1,
                                 neg_half_norm(x0, y0, z0),
                                 neg_half_norm(x1, y1, z1));
        }
        __syncthreads();

        const ulonglong2* pxy = (const ulonglong2*)sxy;
        const ulonglong2* pzw = (const ulonglong2*)szw;

        for (int c = 0; c < NPAIR; c += CPAIRS) {
            float clo[QN], chi[QN];
#pragma unroll
            for (int q = 0; q < QN; q++) { clo[q] = NEG_INF; chi[q] = NEG_INF; }
#pragma unroll
            for (int pp = 0; pp < CPAIRS; pp++) {
                ulonglong2 v0 = pxy[c + pp];   // {bxx, byy} packed
                ulonglong2 v1 = pzw[c + pp];   // {bzz, bww} packed
#pragma unroll
                for (int q = 0; q < QN; q++) {
                    unsigned long long s2 =
                        ffma2_u(axx[q], v0.x, ffma2_u(ayy[q], v0.y,
                                ffma2_u(azz[q], v1.x, v1.y)));
                    float slo, shi;
                    unpack2(s2, slo, shi);     // register aliasing, no SASS
                    clo[q] = fmaxf(clo[q], slo);
                    chi[q] = fmaxf(chi[q], shi);
                }
            }
#pragma unroll
            for (int q = 0; q < QN; q++) {
                float cm = fmaxf(clo[q], chi[q]);
                if (cm > gbest[q]) { gbest[q] = cm; gchunk[q] = t + 2 * c; }
            }
        }
    }

    // Rescan winning chunk (32 targets) from global; bitwise-identical math.
#pragma unroll
    for (int q = 0; q < QN; q++) {
        int base = gchunk[q];
        int bi = -1;
        for (int i = 0; i < CT; i++) {
            const float* p = Tp + 3 * (size_t)(base + i);
            float bx = p[0], by = p[1], bz = p[2];
            float w = neg_half_norm(bx, by, bz);
            float s = fmaf(ax[q], bx, fmaf(ay[q], by, fmaf(az[q], bz, w)));
            if (bi < 0 && s == gbest[q]) bi = base + i;
        }
        if (bi < 0) bi = base;   // unreachable safety

        int qi = qbase + tid + q * 128;
        const float* p = Tp + 3 * (size_t)bi;
        g_part[((size_t)arr * NHALF + half) * NPTS + qi] =
            make_float4(gbest[q], ax[q] - p[0], ay[q] - p[1], az[q] - p[2]);
    }
}

// ---------------------------------------------------------------------------
// Kernel A2: combine target-halves. Lower half wins ties (argmin semantics).
// grid = (NPTS/128, NARR), block = 128.
// ---------------------------------------------------------------------------
__global__ __launch_bounds__(128) void nn_pick_kernel()
{
    const int arr = blockIdx.y;
    const int qi  = blockIdx.x * 128 + threadIdx.x;
    float4 c0 = g_part[((size_t)arr * NHALF + 0) * NPTS + qi];
    float4 c1 = g_part[((size_t)arr * NHALF + 1) * NPTS + qi];
    float4 w = (c1.x > c0.x) ? c1 : c0;      // strict: half 0 keeps ties
    float* r = g_resid + (size_t)arr * NEL + 3 * (size_t)qi;
    r[0] = w.y; r[1] = w.z; r[2] = w.w;
}

// ---------------------------------------------------------------------------
// Block reductions for 512 threads (16 warps)
// ---------------------------------------------------------------------------
__device__ __forceinline__ float blockSum512(float v, float* sb, int tid)
{
#pragma unroll
    for (int o = 16; o; o >>= 1) v += __shfl_down_sync(0xffffffffu, v, o);
    if ((tid & 31) == 0) sb[tid >> 5] = v;
    __syncthreads();
    if (tid < 32) {
        float w = (tid < 16) ? sb[tid] : 0.f;
#pragma unroll
        for (int o = 8; o; o >>= 1) w += __shfl_down_sync(0xffffffffu, w, o);
        if (tid == 0) sb[0] = w;
    }
    __syncthreads();
    float r = sb[0];
    __syncthreads();
    return r;
}

__device__ __forceinline__ unsigned int blockMin512(unsigned int v,
                                                    unsigned int* sb, int tid)
{
#pragma unroll
    for (int o = 16; o; o >>= 1)
        v = min(v, __shfl_down_sync(0xffffffffu, v, o));
    if ((tid & 31) == 0) sb[tid >> 5] = v;
    __syncthreads();
    if (tid < 32) {
        unsigned int w = (tid < 16) ? sb[tid] : 0xFFFFFFFFu;
#pragma unroll
        for (int o = 8; o; o >>= 1)
            w = min(w, __shfl_down_sync(0xffffffffu, w, o));
        if (tid == 0) sb[0] = w;
    }
    __syncthreads();
    unsigned int r = sb[0];
    __syncthreads();
    return r;
}

// ---------------------------------------------------------------------------
// Kernel B: per-array robust masked std via radix-select quantiles.
// ---------------------------------------------------------------------------
__device__ __forceinline__ float key_to_float(unsigned int u)
{
    u = (u & 0x80000000u) ? (u ^ 0x80000000u) : ~u;
    return __uint_as_float(u);
}

__device__ unsigned int radix_select(const unsigned int* uv, int k, int tid,
                                     int* hist, volatile unsigned int* sh2)
{
    unsigned int prefix = 0, pmask = 0;
    int kcur = k;
    for (int shift = 24; shift >= 0; shift -= 8) {
        for (int b = tid; b < 256; b += 512) hist[b] = 0;
        __syncthreads();
        for (int i = tid; i < NEL; i += 512) {
            unsigned int u = uv[i];
            if ((u & pmask) == prefix)
                atomicAdd(&hist[(u >> shift) & 255], 1);
        }
        __syncthreads();
        if (tid < 32) {
            int base = tid * 8;
            int loc[8];
            int s = 0;
#pragma unroll
            for (int j = 0; j < 8; j++) { s += hist[base + j]; loc[j] = s; }
            int incl = s;
#pragma unroll
            for (int o = 1; o < 32; o <<= 1) {
                int up = __shfl_up_sync(0xffffffffu, incl, o);
                if ((tid & 31) >= o) incl += up;
            }
            int excl = incl - s;
#pragma unroll
            for (int j = 0; j < 8; j++) hist[base + j] = loc[j] + excl;
        }
        __syncthreads();
        if (tid < 256) {
            int hi = hist[tid];
            int lo = tid ? hist[tid - 1] : 0;
            if (kcur >= lo && kcur < hi) { sh2[0] = (unsigned)tid; sh2[1] = (unsigned)lo; }
        }
        __syncthreads();
        unsigned int bin = sh2[0];
        kcur -= (int)sh2[1];
        prefix |= bin << shift;
        pmask  |= 255u << shift;
        __syncthreads();
    }
    return prefix;
}

__global__ __launch_bounds__(512) void robust_std_kernel()
{
    extern __shared__ unsigned int uv[];     // NEL keys = 48KB
    __shared__ int hist[256];
    __shared__ float sbuf[32];
    __shared__ volatile unsigned int sh2[2];

    const int arr = blockIdx.x;
    const int tid = threadIdx.x;
    const int T   = 512;
    const float* src = g_resid + (size_t)arr * NEL;

    for (int i = tid; i < NEL; i += T) {
        unsigned int u = __float_as_uint(src[i]);
        u = (u & 0x80000000u) ? ~u : (u | 0x80000000u);
        uv[i] = u;
    }
    __syncthreads();

    const float n1 = (float)(NEL - 1);
    float hlo = 0.15f * n1;  int ilo = (int)hlo;  float flo = hlo - (float)ilo;
    float hhi = 0.85f * n1;  int ihi = (int)hhi;  float fhi = hhi - (float)ihi;

    auto next_val = [&](unsigned int vk, int k) -> unsigned int {
        float lc = 0.f;
        unsigned int lmin = 0xFFFFFFFFu;
        for (int i = tid; i < NEL; i += T) {
            unsigned int u = uv[i];
            if (u <= vk) lc += 1.f;
            else lmin = min(lmin, u);
        }
        float cle = blockSum512(lc, sbuf, tid);
        unsigned int mgt = blockMin512(lmin, (unsigned int*)sbuf, tid);
        return (cle >= (float)(k + 2)) ? vk : mgt;
    };

    unsigned int ulo0 = radix_select(uv, ilo, tid, hist, sh2);
    unsigned int ulo1 = next_val(ulo0, ilo);
    unsigned int uhi0 = radix_select(uv, ihi, tid, hist, sh2);
    unsigned int uhi1 = next_val(uhi0, ihi);

    float vlo0 = key_to_float(ulo0), vlo1 = key_to_float(ulo1);
    float vhi0 = key_to_float(uhi0), vhi1 = key_to_float(uhi1);
    float qlo = vlo0 + flo * (vlo1 - vlo0);
    float qhi = vhi0 + fhi * (vhi1 - vhi0);

    float lc = 0.f, ls = 0.f;
    for (int i = tid; i < NEL; i += T) {
        float v = key_to_float(uv[i]);
        if (v < qlo || v > qhi) { lc += 1.f; ls += v; }
    }
    float cnt = blockSum512(lc, sbuf, tid);
    float sum = blockSum512(ls, sbuf, tid);

    int mode = 0;                 // 0=quantile mask, 1=simple mask, 2=all
    float muA = 0.f, sdA = 0.f;
    if (cnt < 0.5f) {
        float la = 0.f;
        for (int i = tid; i < NEL; i += T) la += key_to_float(uv[i]);
        float sumA = blockSum512(la, sbuf, tid);
        muA = sumA / (float)NEL;
        float lq = 0.f;
        for (int i = tid; i < NEL; i += T) {
            float d = key_to_float(uv[i]) - muA; lq += d * d;
        }
        float ssA = blockSum512(lq, sbuf, tid);
        sdA = sqrtf(ssA / (float)(NEL - 1));
        lc = 0.f; ls = 0.f;
        for (int i = tid; i < NEL; i += T) {
            float v = key_to_float(uv[i]);
            if (fabsf(v - muA) > sdA) { lc += 1.f; ls += v; }
        }
        cnt = blockSum512(lc, sbuf, tid);
        sum = blockSum512(ls, sbuf, tid);
        mode = 1;
        if (cnt < 0.5f) { mode = 2; cnt = (float)NEL; sum = sumA; }
    }

    float mean = sum / cnt;
    float lss = 0.f;
    for (int i = tid; i < NEL; i += T) {
        float v = key_to_float(uv[i]);
        bool w = (mode == 0) ? (v < qlo || v > qhi)
               : (mode == 1) ? (fabsf(v - muA) > sdA)
               : true;
        if (w) { float d = v - mean; lss += d * d; }
    }
    float ssd = blockSum512(lss, sbuf, tid);

    if (tid == 0)
        g_sigma[arr] = sqrtf(ssd / (cnt - 1.0f));
}

// ---------------------------------------------------------------------------
// Kernel C: out = mean_b max(sigma[2b], sigma[2b+1])
// ---------------------------------------------------------------------------
__global__ void finalize_kernel(float* __restrict__ out)
{
    int tid = threadIdx.x;                    // 32 threads
    float v = 0.f;
    if (tid < NB) v = fmaxf(g_sigma[2 * tid], g_sigma[2 * tid + 1]);
#pragma unroll
    for (int o = 16; o; o >>= 1) v += __shfl_down_sync(0xffffffffu, v, o);
    if (tid == 0) out[0] = v * (1.0f / (float)NB);
}

// ---------------------------------------------------------------------------
extern "C" void kernel_launch(void* const* d_in, const int* in_sizes, int n_in,
                              void* d_out, int out_size)
{
    const float* x = (const float*)d_in[0];
    const float* y = (const float*)d_in[1];
    float* out = (float*)d_out;
    (void)in_sizes; (void)n_in; (void)out_size;

    dim3 gridA(16, NHALF, NARR);
    nn_part_kernel<<<gridA, 128>>>(x, y);

    dim3 gridP(NPTS / 128, NARR);
    nn_pick_kernel<<<gridP, 128>>>();

    cudaFuncSetAttribute(robust_std_kernel,
                         cudaFuncAttributeMaxDynamicSharedMemorySize,
                         NEL * (int)sizeof(unsigned int));
    robust_std_kernel<<<NARR, 512, NEL * sizeof(unsigned int)>>>();

    finalize_kernel<<<1, 32>>>(out);
}

// round 5
// speedup vs baseline: 1.9565x; 1.9565x over previous
#include <cuda_runtime.h>
#include <math.h>

#define NPTS   4096
#define NB     16
#define NARR   32           // 16 batches x 2 directions
#define D      3
#define NEL    (NPTS * D)   // 12288 residual elements per array
#define GR     16           // grid resolution per axis
#define NCELL  (GR * GR * GR)

// Scratch (device globals only; no allocation allowed)
__device__ float4 g_sorted[(size_t)NARR * NPTS];        // {x,y,z, orig idx}
__device__ int    g_cellstart[(size_t)NARR * (NCELL + 1)];
__device__ float  g_resid[(size_t)NARR * NEL];
__device__ float  g_sigma[NARR];

// ---------------------------------------------------------------------------
// Kernel G1: build per-set uniform grid (counting sort into cell order).
// One block per set. set = 2*batch + which (which: 0 -> x, 1 -> y).
// ---------------------------------------------------------------------------
__global__ __launch_bounds__(512) void build_grid_kernel(
    const float* __restrict__ x, const float* __restrict__ y)
{
    const int set   = blockIdx.x;        // 0..31
    const int batch = set >> 1;
    const int which = set & 1;
    const float* P = ((which == 0) ? x : y) + (size_t)batch * NPTS * D;

    __shared__ int s_cnt[NCELL];         // counts -> starts -> running offsets
    __shared__ int s_cid[NPTS];
    __shared__ int s_wsum[16];

    const int tid = threadIdx.x;         // 512 threads

    for (int i = tid; i < NCELL; i += 512) s_cnt[i] = 0;
    __syncthreads();

    for (int i = tid; i < NPTS; i += 512) {
        float px = P[3 * i], py = P[3 * i + 1], pz = P[3 * i + 2];
        int cx = min(GR - 1, max(0, (int)(px * (float)GR)));
        int cy = min(GR - 1, max(0, (int)(py * (float)GR)));
        int cz = min(GR - 1, max(0, (int)(pz * (float)GR)));
        int cid = (cz * GR + cy) * GR + cx;
        s_cid[i] = cid;
        atomicAdd(&s_cnt[cid], 1);
    }
    __syncthreads();

    // Exclusive scan of s_cnt[NCELL]: 8 elems/thread + warp scan + warp sums.
    const int base = tid * 8;
    int loc[8];
    int s = 0;
#pragma unroll
    for (int j = 0; j < 8; j++) { int v = s_cnt[base + j]; loc[j] = s; s += v; }
    int incl = s;
#pragma unroll
    for (int o = 1; o < 32; o <<= 1) {
        int u = __shfl_up_sync(0xffffffffu, incl, o);
        if ((tid & 31) >= o) incl += u;
    }
    if ((tid & 31) == 31) s_wsum[tid >> 5] = incl;
    __syncthreads();
    if (tid < 32) {
        int v = (tid < 16) ? s_wsum[tid] : 0;
#pragma unroll
        for (int o = 1; o < 16; o <<= 1) {
            int u = __shfl_up_sync(0xffffffffu, v, o);
            if (tid >= o) v += u;
        }
        if (tid < 16) s_wsum[tid] = v;   // inclusive warp-total scan
    }
    __syncthreads();
    int wexcl = (tid >= 32) ? s_wsum[(tid >> 5) - 1] : 0;
    int texcl = (incl - s) + wexcl;
    __syncthreads();                      // everyone done reading s_cnt
#pragma unroll
    for (int j = 0; j < 8; j++) s_cnt[base + j] = texcl + loc[j];  // starts
    __syncthreads();

    // Publish cell starts BEFORE scatter mutates s_cnt.
    const int gbase = set * (NCELL + 1);
    for (int i = tid; i < NCELL; i += 512) g_cellstart[gbase + i] = s_cnt[i];
    if (tid == 0) g_cellstart[gbase + NCELL] = NPTS;
    __syncthreads();

    // Scatter points into cell order, carrying the original index.
    for (int i = tid; i < NPTS; i += 512) {
        int cid = s_cid[i];
        int off = atomicAdd(&s_cnt[cid], 1);
        g_sorted[(size_t)set * NPTS + off] =
            make_float4(P[3 * i], P[3 * i + 1], P[3 * i + 2],
                        __int_as_float(i));
    }
}

// ---------------------------------------------------------------------------
// Kernel G2: grid NN query. arr = 2*batch + dir; queries = sorted set `arr`,
// targets = sorted set `arr^1`. Expanding Chebyshev rings; after ring r,
// every unscanned cell is > r*h away, so stop when best_d2 <= (r*h)^2.
// Residual written to the query's ORIGINAL index.
// ---------------------------------------------------------------------------
__global__ __launch_bounds__(256) void nn_grid_kernel()
{
    const int arr  = blockIdx.y;          // 0..31
    const int tset = arr ^ 1;
    const int i    = blockIdx.x * 256 + threadIdx.x;   // sorted query index

    float4 q = g_sorted[(size_t)arr * NPTS + i];
    const int qi = __float_as_int(q.w);

    const float4* __restrict__ T  = g_sorted + (size_t)tset * NPTS;
    const int* __restrict__    cs = g_cellstart + (size_t)tset * (NCELL + 1);

    const int cx = min(GR - 1, max(0, (int)(q.x * (float)GR)));
    const int cy = min(GR - 1, max(0, (int)(q.y * (float)GR)));
    const int cz = min(GR - 1, max(0, (int)(q.z * (float)GR)));

    const float h = 1.0f / (float)GR;
    float best = __int_as_float(0x7f800000);
    float bx = 0.f, by = 0.f, bz = 0.f;

    auto scan_cell = [&](int xx, int yy, int zz) {
        int cid = (zz * GR + yy) * GR + xx;
        int s0 = cs[cid], s1 = cs[cid + 1];
        for (int j = s0; j < s1; j++) {
            float4 p = T[j];
            float dx = q.x - p.x, dy = q.y - p.y, dz = q.z - p.z;
            float d2 = fmaf(dx, dx, fmaf(dy, dy, dz * dz));
            if (d2 < best) { best = d2; bx = p.x; by = p.y; bz = p.z; }
        }
    };

    for (int r = 0; r < GR; r++) {
        int zlo = max(cz - r, 0), zhi = min(cz + r, GR - 1);
        for (int zz = zlo; zz <= zhi; zz++) {
            bool zface = (zz == cz - r) || (zz == cz + r);
            int ylo = max(cy - r, 0), yhi = min(cy + r, GR - 1);
            for (int yy = ylo; yy <= yhi; yy++) {
                bool yface = (yy == cy - r) || (yy == cy + r);
                if (zface || yface) {
                    int xlo = max(cx - r, 0), xhi = min(cx + r, GR - 1);
                    for (int xx = xlo; xx <= xhi; xx++)
                        scan_cell(xx, yy, zz);
                } else {
                    int xm = cx - r;
                    if (xm >= 0) scan_cell(xm, yy, zz);
                    int xp = cx + r;
                    if (xp <= GR - 1) scan_cell(xp, yy, zz);
                }
            }
        }
        float bnd = (float)r * h;
        if (best <= bnd * bnd) break;
    }

    float* rr = g_resid + (size_t)arr * NEL + 3 * (size_t)qi;
    rr[0] = q.x - bx;
    rr[1] = q.y - by;
    rr[2] = q.z - bz;
}

// ---------------------------------------------------------------------------
// Block reductions for 512 threads (16 warps)
// ---------------------------------------------------------------------------
__device__ __forceinline__ float blockSum512(float v, float* sb, int tid)
{
#pragma unroll
    for (int o = 16; o; o >>= 1) v += __shfl_down_sync(0xffffffffu, v, o);
    if ((tid & 31) == 0) sb[tid >> 5] = v;
    __syncthreads();
    if (tid < 32) {
        float w = (tid < 16) ? sb[tid] : 0.f;
#pragma unroll
        for (int o = 8; o; o >>= 1) w += __shfl_down_sync(0xffffffffu, w, o);
        if (tid == 0) sb[0] = w;
    }
    __syncthreads();
    float r = sb[0];
    __syncthreads();
    return r;
}

__device__ __forceinline__ unsigned int blockMin512(unsigned int v,
                                                    unsigned int* sb, int tid)
{
#pragma unroll
    for (int o = 16; o; o >>= 1)
        v = min(v, __shfl_down_sync(0xffffffffu, v, o));
    if ((tid & 31) == 0) sb[tid >> 5] = v;
    __syncthreads();
    if (tid < 32) {
        unsigned int w = (tid < 16) ? sb[tid] : 0xFFFFFFFFu;
#pragma unroll
        for (int o = 8; o; o >>= 1)
            w = min(w, __shfl_down_sync(0xffffffffu, w, o));
        if (tid == 0) sb[0] = w;
    }
    __syncthreads();
    unsigned int r = sb[0];
    __syncthreads();
    return r;
}

// ---------------------------------------------------------------------------
// Kernel B: per-array robust masked std via radix-select quantiles.
// ---------------------------------------------------------------------------
__device__ __forceinline__ float key_to_float(unsigned int u)
{
    u = (u & 0x80000000u) ? (u ^ 0x80000000u) : ~u;
    return __uint_as_float(u);
}

__device__ unsigned int radix_select(const unsigned int* uv, int k, int tid,
                                     int* hist, volatile unsigned int* sh2)
{
    unsigned int prefix = 0, pmask = 0;
    int kcur = k;
    for (int shift = 24; shift >= 0; shift -= 8) {
        for (int b = tid; b < 256; b += 512) hist[b] = 0;
        __syncthreads();
        for (int i = tid; i < NEL; i += 512) {
            unsigned int u = uv[i];
            if ((u & pmask) == prefix)
                atomicAdd(&hist[(u >> shift) & 255], 1);
        }
        __syncthreads();
        if (tid < 32) {
            int base = tid * 8;
            int loc[8];
            int s = 0;
#pragma unroll
            for (int j = 0; j < 8; j++) { s += hist[base + j]; loc[j] = s; }
            int incl = s;
#pragma unroll
            for (int o = 1; o < 32; o <<= 1) {
                int up = __shfl_up_sync(0xffffffffu, incl, o);
                if ((tid & 31) >= o) incl += up;
            }
            int excl = incl - s;
#pragma unroll
            for (int j = 0; j < 8; j++) hist[base + j] = loc[j] + excl;
        }
        __syncthreads();
        if (tid < 256) {
            int hi = hist[tid];
            int lo = tid ? hist[tid - 1] : 0;
            if (kcur >= lo && kcur < hi) { sh2[0] = (unsigned)tid; sh2[1] = (unsigned)lo; }
        }
        __syncthreads();
        unsigned int bin = sh2[0];
        kcur -= (int)sh2[1];
        prefix |= bin << shift;
        pmask  |= 255u << shift;
        __syncthreads();
    }
    return prefix;
}

__global__ __launch_bounds__(512) void robust_std_kernel()
{
    extern __shared__ unsigned int uv[];     // NEL keys = 48KB
    __shared__ int hist[256];
    __shared__ float sbuf[32];
    __shared__ volatile unsigned int sh2[2];

    const int arr = blockIdx.x;
    const int tid = threadIdx.x;
    const int T   = 512;
    const float* src = g_resid + (size_t)arr * NEL;

    for (int i = tid; i < NEL; i += T) {
        unsigned int u = __float_as_uint(src[i]);
        u = (u & 0x80000000u) ? ~u : (u | 0x80000000u);
        uv[i] = u;
    }
    __syncthreads();

    const float n1 = (float)(NEL - 1);
    float hlo = 0.15f * n1;  int ilo = (int)hlo;  float flo = hlo - (float)ilo;
    float hhi = 0.85f * n1;  int ihi = (int)hhi;  float fhi = hhi - (float)ihi;

    auto next_val = [&](unsigned int vk, int k) -> unsigned int {
        float lc = 0.f;
        unsigned int lmin = 0xFFFFFFFFu;
        for (int i = tid; i < NEL; i += T) {
            unsigned int u = uv[i];
            if (u <= vk) lc += 1.f;
            else lmin = min(lmin, u);
        }
        float cle = blockSum512(lc, sbuf, tid);
        unsigned int mgt = blockMin512(lmin, (unsigned int*)sbuf, tid);
        return (cle >= (float)(k + 2)) ? vk : mgt;
    };

    unsigned int ulo0 = radix_select(uv, ilo, tid, hist, sh2);
    unsigned int ulo1 = next_val(ulo0, ilo);
    unsigned int uhi0 = radix_select(uv, ihi, tid, hist, sh2);
    unsigned int uhi1 = next_val(uhi0, ihi);

    float vlo0 = key_to_float(ulo0), vlo1 = key_to_float(ulo1);
    float vhi0 = key_to_float(uhi0), vhi1 = key_to_float(uhi1);
    float qlo = vlo0 + flo * (vlo1 - vlo0);
    float qhi = vhi0 + fhi * (vhi1 - vhi0);

    float lc = 0.f, ls = 0.f;
    for (int i = tid; i < NEL; i += T) {
        float v = key_to_float(uv[i]);
        if (v < qlo || v > qhi) { lc += 1.f; ls += v; }
    }
    float cnt = blockSum512(lc, sbuf, tid);
    float sum = blockSum512(ls, sbuf, tid);

    int mode = 0;                 // 0=quantile mask, 1=simple mask, 2=all
    float muA = 0.f, sdA = 0.f;
    if (cnt < 0.5f) {
        float la = 0.f;
        for (int i = tid; i < NEL; i += T) la += key_to_float(uv[i]);
        float sumA = blockSum512(la, sbuf, tid);
        muA = sumA / (float)NEL;
        float lq = 0.f;
        for (int i = tid; i < NEL; i += T) {
            float d = key_to_float(uv[i]) - muA; lq += d * d;
        }
        float ssA = blockSum512(lq, sbuf, tid);
        sdA = sqrtf(ssA / (float)(NEL - 1));
        lc = 0.f; ls = 0.f;
        for (int i = tid; i < NEL; i += T) {
            float v = key_to_float(uv[i]);
            if (fabsf(v - muA) > sdA) { lc += 1.f; ls += v; }
        }
        cnt = blockSum512(lc, sbuf, tid);
        sum = blockSum512(ls, sbuf, tid);
        mode = 1;
        if (cnt < 0.5f) { mode = 2; cnt = (float)NEL; sum = sumA; }
    }

    float mean = sum / cnt;
    float lss = 0.f;
    for (int i = tid; i < NEL; i += T) {
        float v = key_to_float(uv[i]);
        bool w = (mode == 0) ? (v < qlo || v > qhi)
               : (mode == 1) ? (fabsf(v - muA) > sdA)
               : true;
        if (w) { float d = v - mean; lss += d * d; }
    }
    float ssd = blockSum512(lss, sbuf, tid);

    if (tid == 0)
        g_sigma[arr] = sqrtf(ssd / (cnt - 1.0f));
}

// ---------------------------------------------------------------------------
// Kernel C: out = mean_b max(sigma[2b], sigma[2b+1])
// ---------------------------------------------------------------------------
__global__ void finalize_kernel(float* __restrict__ out)
{
    int tid = threadIdx.x;                    // 32 threads
    float v = 0.f;
    if (tid < NB) v = fmaxf(g_sigma[2 * tid], g_sigma[2 * tid + 1]);
#pragma unroll
    for (int o = 16; o; o >>= 1) v += __shfl_down_sync(0xffffffffu, v, o);
    if (tid == 0) out[0] = v * (1.0f / (float)NB);
}

// ---------------------------------------------------------------------------
extern "C" void kernel_launch(void* const* d_in, const int* in_sizes, int n_in,
                              void* d_out, int out_size)
{
    const float* x = (const float*)d_in[0];
    const float* y = (const float*)d_in[1];
    float* out = (float*)d_out;
    (void)in_sizes; (void)n_in; (void)out_size;

    build_grid_kernel<<<NARR, 512>>>(x, y);

    dim3 gridQ(NPTS / 256, NARR);
    nn_grid_kernel<<<gridQ, 256>>>();

    cudaFuncSetAttribute(robust_std_kernel,
                         cudaFuncAttributeMaxDynamicSharedMemorySize,
                         NEL * (int)sizeof(unsigned int));
    robust_std_kernel<<<NARR, 512, NEL * sizeof(unsigned int)>>>();

    finalize_kernel<<<1, 32>>>(out);
}

// round 6
// speedup vs baseline: 2.7880x; 1.4250x over previous
#include <cuda_runtime.h>
#include <math.h>

#define NPTS   4096
#define NB     16
#define NARR   32           // 16 batches x 2 directions
#define D      3
#define NEL    (NPTS * D)   // 12288 residual elements per array
#define GR     16           // grid resolution per axis
#define NCELL  (GR * GR * GR)

// Scratch (device globals only; no allocation allowed)
__device__ float4 g_sorted[(size_t)NARR * NPTS];        // {x,y,z,_}
__device__ int    g_cellstart[(size_t)NARR * (NCELL + 1)];
__device__ float  g_resid[(size_t)NARR * NEL];          // SoA: [arr][coord][i]
__device__ float  g_sigma[NARR];
__device__ int    g_done;                                // zero-init, self-reset

// ---------------------------------------------------------------------------
// Kernel G1: build per-set uniform grid (counting sort into cell order).
// One block per set. set = 2*batch + which (which: 0 -> x, 1 -> y).
// ---------------------------------------------------------------------------
__global__ __launch_bounds__(512) void build_grid_kernel(
    const float* __restrict__ x, const float* __restrict__ y)
{
    const int set   = blockIdx.x;        // 0..31
    const int batch = set >> 1;
    const int which = set & 1;
    const float* P = ((which == 0) ? x : y) + (size_t)batch * NPTS * D;

    __shared__ int s_cnt[NCELL];
    __shared__ int s_cid[NPTS];
    __shared__ int s_wsum[16];

    const int tid = threadIdx.x;         // 512 threads

    for (int i = tid; i < NCELL; i += 512) s_cnt[i] = 0;
    __syncthreads();

    for (int i = tid; i < NPTS; i += 512) {
        float px = P[3 * i], py = P[3 * i + 1], pz = P[3 * i + 2];
        int cx = min(GR - 1, max(0, (int)(px * (float)GR)));
        int cy = min(GR - 1, max(0, (int)(py * (float)GR)));
        int cz = min(GR - 1, max(0, (int)(pz * (float)GR)));
        int cid = (cz * GR + cy) * GR + cx;
        s_cid[i] = cid;
        atomicAdd(&s_cnt[cid], 1);
    }
    __syncthreads();

    // Exclusive scan of s_cnt[NCELL]: 8 elems/thread + warp scan + warp sums.
    const int base = tid * 8;
    int loc[8];
    int s = 0;
#pragma unroll
    for (int j = 0; j < 8; j++) { int v = s_cnt[base + j]; loc[j] = s; s += v; }
    int incl = s;
#pragma unroll
    for (int o = 1; o < 32; o <<= 1) {
        int u = __shfl_up_sync(0xffffffffu, incl, o);
        if ((tid & 31) >= o) incl += u;
    }
    if ((tid & 31) == 31) s_wsum[tid >> 5] = incl;
    __syncthreads();
    if (tid < 32) {
        int v = (tid < 16) ? s_wsum[tid] : 0;
#pragma unroll
        for (int o = 1; o < 16; o <<= 1) {
            int u = __shfl_up_sync(0xffffffffu, v, o);
            if (tid >= o) v += u;
        }
        if (tid < 16) s_wsum[tid] = v;
    }
    __syncthreads();
    int wexcl = (tid >= 32) ? s_wsum[(tid >> 5) - 1] : 0;
    int texcl = (incl - s) + wexcl;
    __syncthreads();
#pragma unroll
    for (int j = 0; j < 8; j++) s_cnt[base + j] = texcl + loc[j];  // starts
    __syncthreads();

    const int gbase = set * (NCELL + 1);
    for (int i = tid; i < NCELL; i += 512) g_cellstart[gbase + i] = s_cnt[i];
    if (tid == 0) g_cellstart[gbase + NCELL] = NPTS;
    __syncthreads();

    for (int i = tid; i < NPTS; i += 512) {
        int cid = s_cid[i];
        int off = atomicAdd(&s_cnt[cid], 1);
        g_sorted[(size_t)set * NPTS + off] =
            make_float4(P[3 * i], P[3 * i + 1], P[3 * i + 2], 0.f);
    }
}

// ---------------------------------------------------------------------------
// Kernel G2: grid NN query with x-row-merged range scans.
// Cells consecutive in x are contiguous in the sorted array, so a full
// (y,z) row of a ring is ONE contiguous point range. Residuals written SoA
// in sorted order (robust std is permutation-invariant).
// ---------------------------------------------------------------------------
__global__ __launch_bounds__(256) void nn_grid_kernel()
{
    const int arr  = blockIdx.y;          // 0..31
    const int tset = arr ^ 1;
    const int i    = blockIdx.x * 256 + threadIdx.x;   // sorted query index

    float4 q = g_sorted[(size_t)arr * NPTS + i];

    const float4* __restrict__ T  = g_sorted + (size_t)tset * NPTS;
    const int* __restrict__    cs = g_cellstart + (size_t)tset * (NCELL + 1);

    const int cx = min(GR - 1, max(0, (int)(q.x * (float)GR)));
    const int cy = min(GR - 1, max(0, (int)(q.y * (float)GR)));
    const int cz = min(GR - 1, max(0, (int)(q.z * (float)GR)));

    const float h = 1.0f / (float)GR;
    float best = __int_as_float(0x7f800000);
    float bx = 0.f, by = 0.f, bz = 0.f;

    // scan contiguous point range covering cells [c0 .. c1] (same y,z row)
    auto scan_range = [&](int c0, int c1) {
        int s0 = cs[c0], s1 = cs[c1 + 1];
        for (int j = s0; j < s1; j++) {
            float4 p = T[j];
            float dx = q.x - p.x, dy = q.y - p.y, dz = q.z - p.z;
            float d2 = fmaf(dx, dx, fmaf(dy, dy, dz * dz));
            if (d2 < best) { best = d2; bx = p.x; by = p.y; bz = p.z; }
        }
    };

    for (int r = 0; r < GR; r++) {
        int zlo = max(cz - r, 0), zhi = min(cz + r, GR - 1);
        int xlo = max(cx - r, 0), xhi = min(cx + r, GR - 1);
        for (int zz = zlo; zz <= zhi; zz++) {
            bool zface = (zz == cz - r) || (zz == cz + r);
            int ylo = max(cy - r, 0), yhi = min(cy + r, GR - 1);
            for (int yy = ylo; yy <= yhi; yy++) {
                bool yface = (yy == cy - r) || (yy == cy + r);
                int rowb = (zz * GR + yy) * GR;
                if (zface || yface) {
                    scan_range(rowb + xlo, rowb + xhi);    // full x-run
                } else {
                    int xm = cx - r;
                    if (xm >= 0) scan_range(rowb + xm, rowb + xm);
                    int xp = cx + r;
                    if (xp <= GR - 1) scan_range(rowb + xp, rowb + xp);
                }
            }
        }
        float bnd = (float)r * h;
        if (best <= bnd * bnd) break;
    }

    float* rr = g_resid + (size_t)arr * NEL;
    rr[0 * NPTS + i] = q.x - bx;      // coalesced SoA stores
    rr[1 * NPTS + i] = q.y - by;
    rr[2 * NPTS + i] = q.z - bz;
}

// ---------------------------------------------------------------------------
// Block reductions for 512 threads (16 warps)
// ---------------------------------------------------------------------------
__device__ __forceinline__ float blockSum512(float v, float* sb, int tid)
{
#pragma unroll
    for (int o = 16; o; o >>= 1) v += __shfl_down_sync(0xffffffffu, v, o);
    if ((tid & 31) == 0) sb[tid >> 5] = v;
    __syncthreads();
    if (tid < 32) {
        float w = (tid < 16) ? sb[tid] : 0.f;
#pragma unroll
        for (int o = 8; o; o >>= 1) w += __shfl_down_sync(0xffffffffu, w, o);
        if (tid == 0) sb[0] = w;
    }
    __syncthreads();
    float r = sb[0];
    __syncthreads();
    return r;
}

__device__ __forceinline__ unsigned int blockMin512(unsigned int v,
                                                    unsigned int* sb, int tid)
{
#pragma unroll
    for (int o = 16; o; o >>= 1)
        v = min(v, __shfl_down_sync(0xffffffffu, v, o));
    if ((tid & 31) == 0) sb[tid >> 5] = v;
    __syncthreads();
    if (tid < 32) {
        unsigned int w = (tid < 16) ? sb[tid] : 0xFFFFFFFFu;
#pragma unroll
        for (int o = 8; o; o >>= 1)
            w = min(w, __shfl_down_sync(0xffffffffu, w, o));
        if (tid == 0) sb[0] = w;
    }
    __syncthreads();
    unsigned int r = sb[0];
    __syncthreads();
    return r;
}

// ---------------------------------------------------------------------------
// Kernel B: robust masked std. Dual-rank radix select (shared histogram
// passes), fused finalize via completion counter.
// ---------------------------------------------------------------------------
__device__ __forceinline__ float key_to_float(unsigned int u)
{
    u = (u & 0x80000000u) ? (u ^ 0x80000000u) : ~u;
    return __uint_as_float(u);
}

// warp-collective scan of 256-bin histogram -> inclusive
__device__ __forceinline__ void scan256(int* hh, int lane)
{
    int base = lane * 8;
    int loc[8];
    int s = 0;
#pragma unroll
    for (int j = 0; j < 8; j++) { s += hh[base + j]; loc[j] = s; }
    int incl = s;
#pragma unroll
    for (int o = 1; o < 32; o <<= 1) {
        int up = __shfl_up_sync(0xffffffffu, incl, o);
        if (lane >= o) incl += up;
    }
    int excl = incl - s;
#pragma unroll
    for (int j = 0; j < 8; j++) hh[base + j] = loc[j] + excl;
}

__global__ __launch_bounds__(512) void robust_std_kernel(float* __restrict__ out)
{
    extern __shared__ unsigned int uv[];     // NEL keys = 48KB
    __shared__ int h0[256], h1[256];
    __shared__ float sbuf[32];
    __shared__ volatile unsigned int sh4[4];

    const int arr = blockIdx.x;
    const int tid = threadIdx.x;
    const int T   = 512;
    const float* src = g_resid + (size_t)arr * NEL;

    for (int i = tid; i < NEL; i += T) {
        unsigned int u = __float_as_uint(src[i]);
        u = (u & 0x80000000u) ? ~u : (u | 0x80000000u);
        uv[i] = u;
    }
    __syncthreads();

    const float n1 = (float)(NEL - 1);
    float hlo = 0.15f * n1;  int ilo = (int)hlo;  float flo = hlo - (float)ilo;
    float hhi = 0.85f * n1;  int ihi = (int)hhi;  float fhi = hhi - (float)ihi;

    // ---- dual-rank radix select: ranks ilo and ihi in one histogram sweep ---
    unsigned int plo = 0, phi = 0, pmask = 0;
    int kl = ilo, kh = ihi;
    for (int shift = 24; shift >= 0; shift -= 8) {
        bool same = (plo == phi);     // round 1: both prefixes empty
        for (int b = tid; b < 256; b += T) { h0[b] = 0; h1[b] = 0; }
        __syncthreads();
        for (int i = tid; i < NEL; i += T) {
            unsigned int u = uv[i];
            if ((u & pmask) == plo) atomicAdd(&h0[(u >> shift) & 255], 1);
            if (!same && (u & pmask) == phi)
                atomicAdd(&h1[(u >> shift) & 255], 1);
        }
        __syncthreads();
        if (tid < 32) scan256(h0, tid);
        else if (tid < 64 && !same) scan256(h1, tid - 32);
        __syncthreads();
        if (tid < 256) {
            int hi = h0[tid];
            int lo = tid ? h0[tid - 1] : 0;
            if (kl >= lo && kl < hi) { sh4[0] = (unsigned)tid; sh4[1] = (unsigned)lo; }
        } else {
            int t2 = tid - 256;
            int* hs = same ? h0 : h1;
            int hi = hs[t2];
            int lo = t2 ? hs[t2 - 1] : 0;
            if (kh >= lo && kh < hi) { sh4[2] = (unsigned)t2; sh4[3] = (unsigned)lo; }
        }
        __syncthreads();
        plo |= sh4[0] << shift;  kl -= (int)sh4[1];
        phi |= sh4[2] << shift;  kh -= (int)sh4[3];
        pmask |= 255u << shift;
        __syncthreads();
    }
    unsigned int ulo0 = plo, uhi0 = phi;

    // ---- next-rank values for both quantiles in ONE pass --------------------
    float clo = 0.f, chi = 0.f;
    unsigned int mlo = 0xFFFFFFFFu, mhi = 0xFFFFFFFFu;
    for (int i = tid; i < NEL; i += T) {
        unsigned int u = uv[i];
        if (u <= ulo0) clo += 1.f; else mlo = min(mlo, u);
        if (u <= uhi0) chi += 1.f; else mhi = min(mhi, u);
    }
    float cleL = blockSum512(clo, sbuf, tid);
    float cleH = blockSum512(chi, sbuf, tid);
    unsigned int mgtL = blockMin512(mlo, (unsigned int*)sbuf, tid);
    unsigned int mgtH = blockMin512(mhi, (unsigned int*)sbuf, tid);
    unsigned int ulo1 = (cleL >= (float)(ilo + 2)) ? ulo0 : mgtL;
    unsigned int uhi1 = (cleH >= (float)(ihi + 2)) ? uhi0 : mgtH;

    float vlo0 = key_to_float(ulo0), vlo1 = key_to_float(ulo1);
    float vhi0 = key_to_float(uhi0), vhi1 = key_to_float(uhi1);
    float qlo = vlo0 + flo * (vlo1 - vlo0);
    float qhi = vhi0 + fhi * (vhi1 - vhi0);

    // ---- quantile-outlier mask (Z_INDEX=0) -----------------------------------
    float lc = 0.f, ls = 0.f;
    for (int i = tid; i < NEL; i += T) {
        float v = key_to_float(uv[i]);
        if (v < qlo || v > qhi) { lc += 1.f; ls += v; }
    }
    float cnt = blockSum512(lc, sbuf, tid);
    float sum = blockSum512(ls, sbuf, tid);

    int mode = 0;                 // 0=quantile mask, 1=simple mask, 2=all
    float muA = 0.f, sdA = 0.f;
    if (cnt < 0.5f) {
        float la = 0.f;
        for (int i = tid; i < NEL; i += T) la += key_to_float(uv[i]);
        float sumA = blockSum512(la, sbuf, tid);
        muA = sumA / (float)NEL;
        float lq = 0.f;
        for (int i = tid; i < NEL; i += T) {
            float d = key_to_float(uv[i]) - muA; lq += d * d;
        }
        float ssA = blockSum512(lq, sbuf, tid);
        sdA = sqrtf(ssA / (float)(NEL - 1));
        lc = 0.f; ls = 0.f;
        for (int i = tid; i < NEL; i += T) {
            float v = key_to_float(uv[i]);
            if (fabsf(v - muA) > sdA) { lc += 1.f; ls += v; }
        }
        cnt = blockSum512(lc, sbuf, tid);
        sum = blockSum512(ls, sbuf, tid);
        mode = 1;
        if (cnt < 0.5f) { mode = 2; cnt = (float)NEL; sum = sumA; }
    }

    float mean = sum / cnt;
    float lss = 0.f;
    for (int i = tid; i < NEL; i += T) {
        float v = key_to_float(uv[i]);
        bool w = (mode == 0) ? (v < qlo || v > qhi)
               : (mode == 1) ? (fabsf(v - muA) > sdA)
               : true;
        if (w) { float d = v - mean; lss += d * d; }
    }
    float ssd = blockSum512(lss, sbuf, tid);

    // ---- publish sigma; last block to finish computes the final output ------
    if (tid == 0) {
        g_sigma[arr] = sqrtf(ssd / (cnt - 1.0f));
        __threadfence();
        int done = atomicAdd(&g_done, 1);
        if (done == NARR - 1) {
            float acc = 0.f;
#pragma unroll
            for (int b = 0; b < NB; b++)
                acc += fmaxf(g_sigma[2 * b], g_sigma[2 * b + 1]);
            out[0] = acc * (1.0f / (float)NB);
            g_done = 0;           // reset for next graph replay
        }
    }
}

// ---------------------------------------------------------------------------
extern "C" void kernel_launch(void* const* d_in, const int* in_sizes, int n_in,
                              void* d_out, int out_size)
{
    const float* x = (const float*)d_in[0];
    const float* y = (const float*)d_in[1];
    float* out = (float*)d_out;
    (void)in_sizes; (void)n_in; (void)out_size;

    build_grid_kernel<<<NARR, 512>>>(x, y);

    dim3 gridQ(NPTS / 256, NARR);
    nn_grid_kernel<<<gridQ, 256>>>();

    cudaFuncSetAttribute(robust_std_kernel,
                         cudaFuncAttributeMaxDynamicSharedMemorySize,
                         NEL * (int)sizeof(unsigned int));
    robust_std_kernel<<<NARR, 512, NEL * sizeof(unsigned int)>>>(out);
}

// round 7
// speedup vs baseline: 2.8351x; 1.0169x over previous
#include <cuda_runtime.h>
#include <math.h>

#define NPTS   4096
#define NB     16
#define NARR   32           // 16 batches x 2 directions
#define D      3
#define NEL    (NPTS * D)   // 12288 residual elements per array
#define GR     16           // grid resolution per axis
#define NCELL  (GR * GR * GR)

// Scratch (device globals only; no allocation allowed)
__device__ float4 g_sorted[(size_t)NARR * NPTS];        // {x,y,z,_}
__device__ int    g_cellstart[(size_t)NARR * (NCELL + 1)];
__device__ float  g_resid[(size_t)NARR * NEL];          // SoA: [arr][coord][i]
__device__ float  g_sigma[NARR];
__device__ int    g_done;                                // zero-init, self-reset

// ---------------------------------------------------------------------------
// Kernel G1: build per-set uniform grid (counting sort into cell order).
// One block (1024 threads) per set. set = 2*batch + which (0 -> x, 1 -> y).
// ---------------------------------------------------------------------------
__global__ __launch_bounds__(1024) void build_grid_kernel(
    const float* __restrict__ x, const float* __restrict__ y)
{
    const int set   = blockIdx.x;        // 0..31
    const int batch = set >> 1;
    const int which = set & 1;
    const float* P = ((which == 0) ? x : y) + (size_t)batch * NPTS * D;

    __shared__ int s_cnt[NCELL];
    __shared__ int s_cid[NPTS];
    __shared__ int s_wsum[32];

    const int tid = threadIdx.x;         // 1024 threads

    for (int i = tid; i < NCELL; i += 1024) s_cnt[i] = 0;
    __syncthreads();

    for (int i = tid; i < NPTS; i += 1024) {
        float px = P[3 * i], py = P[3 * i + 1], pz = P[3 * i + 2];
        int cx = min(GR - 1, max(0, (int)(px * (float)GR)));
        int cy = min(GR - 1, max(0, (int)(py * (float)GR)));
        int cz = min(GR - 1, max(0, (int)(pz * (float)GR)));
        int cid = (cz * GR + cy) * GR + cx;
        s_cid[i] = cid;
        atomicAdd(&s_cnt[cid], 1);
    }
    __syncthreads();

    // Exclusive scan of s_cnt[NCELL]: 4 elems/thread + warp scan + warp sums.
    const int base = tid * 4;
    int loc[4];
    int s = 0;
#pragma unroll
    for (int j = 0; j < 4; j++) { int v = s_cnt[base + j]; loc[j] = s; s += v; }
    int incl = s;
#pragma unroll
    for (int o = 1; o < 32; o <<= 1) {
        int u = __shfl_up_sync(0xffffffffu, incl, o);
        if ((tid & 31) >= o) incl += u;
    }
    if ((tid & 31) == 31) s_wsum[tid >> 5] = incl;
    __syncthreads();
    if (tid < 32) {
        int v = s_wsum[tid];
#pragma unroll
        for (int o = 1; o < 32; o <<= 1) {
            int u = __shfl_up_sync(0xffffffffu, v, o);
            if (tid >= o) v += u;
        }
        s_wsum[tid] = v;                 // inclusive warp-total scan
    }
    __syncthreads();
    int wexcl = (tid >= 32) ? s_wsum[(tid >> 5) - 1] : 0;
    int texcl = (incl - s) + wexcl;
    __syncthreads();
#pragma unroll
    for (int j = 0; j < 4; j++) s_cnt[base + j] = texcl + loc[j];  // starts
    __syncthreads();

    const int gbase = set * (NCELL + 1);
    for (int i = tid; i < NCELL; i += 1024) g_cellstart[gbase + i] = s_cnt[i];
    if (tid == 0) g_cellstart[gbase + NCELL] = NPTS;
    __syncthreads();

    for (int i = tid; i < NPTS; i += 1024) {
        int cid = s_cid[i];
        int off = atomicAdd(&s_cnt[cid], 1);
        g_sorted[(size_t)set * NPTS + off] =
            make_float4(P[3 * i], P[3 * i + 1], P[3 * i + 2], 0.f);
    }
}

// ---------------------------------------------------------------------------
// Kernel G2: grid NN query with x-row-merged range scans.
// Residuals written SoA in sorted order (robust std is permutation-invariant).
// ---------------------------------------------------------------------------
__global__ __launch_bounds__(256) void nn_grid_kernel()
{
    const int arr  = blockIdx.y;          // 0..31
    const int tset = arr ^ 1;
    const int i    = blockIdx.x * 256 + threadIdx.x;   // sorted query index

    float4 q = g_sorted[(size_t)arr * NPTS + i];

    const float4* __restrict__ T  = g_sorted + (size_t)tset * NPTS;
    const int* __restrict__    cs = g_cellstart + (size_t)tset * (NCELL + 1);

    const int cx = min(GR - 1, max(0, (int)(q.x * (float)GR)));
    const int cy = min(GR - 1, max(0, (int)(q.y * (float)GR)));
    const int cz = min(GR - 1, max(0, (int)(q.z * (float)GR)));

    const float h = 1.0f / (float)GR;
    float best = __int_as_float(0x7f800000);
    float bx = 0.f, by = 0.f, bz = 0.f;

    auto scan_range = [&](int c0, int c1) {
        int s0 = cs[c0], s1 = cs[c1 + 1];
        for (int j = s0; j < s1; j++) {
            float4 p = T[j];
            float dx = q.x - p.x, dy = q.y - p.y, dz = q.z - p.z;
            float d2 = fmaf(dx, dx, fmaf(dy, dy, dz * dz));
            if (d2 < best) { best = d2; bx = p.x; by = p.y; bz = p.z; }
        }
    };

    for (int r = 0; r < GR; r++) {
        int zlo = max(cz - r, 0), zhi = min(cz + r, GR - 1);
        int xlo = max(cx - r, 0), xhi = min(cx + r, GR - 1);
        for (int zz = zlo; zz <= zhi; zz++) {
            bool zface = (zz == cz - r) || (zz == cz + r);
            int ylo = max(cy - r, 0), yhi = min(cy + r, GR - 1);
            for (int yy = ylo; yy <= yhi; yy++) {
                bool yface = (yy == cy - r) || (yy == cy + r);
                int rowb = (zz * GR + yy) * GR;
                if (zface || yface) {
                    scan_range(rowb + xlo, rowb + xhi);
                } else {
                    int xm = cx - r;
                    if (xm >= 0) scan_range(rowb + xm, rowb + xm);
                    int xp = cx + r;
                    if (xp <= GR - 1) scan_range(rowb + xp, rowb + xp);
                }
            }
        }
        float bnd = (float)r * h;
        if (best <= bnd * bnd) break;
    }

    float* rr = g_resid + (size_t)arr * NEL;
    rr[0 * NPTS + i] = q.x - bx;
    rr[1 * NPTS + i] = q.y - by;
    rr[2 * NPTS + i] = q.z - bz;
}

// ---------------------------------------------------------------------------
// Block reductions for 1024 threads (32 warps)
// ---------------------------------------------------------------------------
__device__ __forceinline__ float blockSum1024(float v, float* sb, int tid)
{
#pragma unroll
    for (int o = 16; o; o >>= 1) v += __shfl_down_sync(0xffffffffu, v, o);
    if ((tid & 31) == 0) sb[tid >> 5] = v;
    __syncthreads();
    if (tid < 32) {
        float w = sb[tid];
#pragma unroll
        for (int o = 16; o; o >>= 1) w += __shfl_down_sync(0xffffffffu, w, o);
        if (tid == 0) sb[0] = w;
    }
    __syncthreads();
    float r = sb[0];
    __syncthreads();
    return r;
}

__device__ __forceinline__ unsigned int blockMin1024(unsigned int v,
                                                     unsigned int* sb, int tid)
{
#pragma unroll
    for (int o = 16; o; o >>= 1)
        v = min(v, __shfl_down_sync(0xffffffffu, v, o));
    if ((tid & 31) == 0) sb[tid >> 5] = v;
    __syncthreads();
    if (tid < 32) {
        unsigned int w = sb[tid];
#pragma unroll
        for (int o = 16; o; o >>= 1)
            w = min(w, __shfl_down_sync(0xffffffffu, w, o));
        if (tid == 0) sb[0] = w;
    }
    __syncthreads();
    unsigned int r = sb[0];
    __syncthreads();
    return r;
}

// ---------------------------------------------------------------------------
// Kernel B: robust masked std. Dual-rank radix select, fused (cnt,sum,sumsq)
// mask pass, fused finalize via completion counter. 1024 threads.
// ---------------------------------------------------------------------------
__device__ __forceinline__ float key_to_float(unsigned int u)
{
    u = (u & 0x80000000u) ? (u ^ 0x80000000u) : ~u;
    return __uint_as_float(u);
}

__device__ __forceinline__ void scan256(int* hh, int lane)
{
    int base = lane * 8;
    int loc[8];
    int s = 0;
#pragma unroll
    for (int j = 0; j < 8; j++) { s += hh[base + j]; loc[j] = s; }
    int incl = s;
#pragma unroll
    for (int o = 1; o < 32; o <<= 1) {
        int up = __shfl_up_sync(0xffffffffu, incl, o);
        if (lane >= o) incl += up;
    }
    int excl = incl - s;
#pragma unroll
    for (int j = 0; j < 8; j++) hh[base + j] = loc[j] + excl;
}

__global__ __launch_bounds__(1024) void robust_std_kernel(float* __restrict__ out)
{
    extern __shared__ unsigned int uv[];     // NEL keys = 48KB
    __shared__ int h0[256], h1[256];
    __shared__ float sbuf[32];
    __shared__ volatile unsigned int sh4[4];

    const int arr = blockIdx.x;
    const int tid = threadIdx.x;
    const int T   = 1024;
    const float* src = g_resid + (size_t)arr * NEL;

    for (int i = tid; i < NEL; i += T) {
        unsigned int u = __float_as_uint(src[i]);
        u = (u & 0x80000000u) ? ~u : (u | 0x80000000u);
        uv[i] = u;
    }
    __syncthreads();

    const float n1 = (float)(NEL - 1);
    float hlo = 0.15f * n1;  int ilo = (int)hlo;  float flo = hlo - (float)ilo;
    float hhi = 0.85f * n1;  int ihi = (int)hhi;  float fhi = hhi - (float)ihi;

    // ---- dual-rank radix select --------------------------------------------
    unsigned int plo = 0, phi = 0, pmask = 0;
    int kl = ilo, kh = ihi;
    for (int shift = 24; shift >= 0; shift -= 8) {
        bool same = (plo == phi);     // round 1: both prefixes empty
        if (tid < 256) { h0[tid] = 0; h1[tid] = 0; }
        __syncthreads();
        for (int i = tid; i < NEL; i += T) {
            unsigned int u = uv[i];
            if ((u & pmask) == plo) atomicAdd(&h0[(u >> shift) & 255], 1);
            if (!same && (u & pmask) == phi)
                atomicAdd(&h1[(u >> shift) & 255], 1);
        }
        __syncthreads();
        if (tid < 32) scan256(h0, tid);
        else if (tid < 64 && !same) scan256(h1, tid - 32);
        __syncthreads();
        if (tid < 256) {
            int hi = h0[tid];
            int lo = tid ? h0[tid - 1] : 0;
            if (kl >= lo && kl < hi) { sh4[0] = (unsigned)tid; sh4[1] = (unsigned)lo; }
        } else if (tid < 512) {
            int t2 = tid - 256;
            int* hs = same ? h0 : h1;
            int hi = hs[t2];
            int lo = t2 ? hs[t2 - 1] : 0;
            if (kh >= lo && kh < hi) { sh4[2] = (unsigned)t2; sh4[3] = (unsigned)lo; }
        }
        __syncthreads();
        plo |= sh4[0] << shift;  kl -= (int)sh4[1];
        phi |= sh4[2] << shift;  kh -= (int)sh4[3];
        pmask |= 255u << shift;
        __syncthreads();
    }
    unsigned int ulo0 = plo, uhi0 = phi;

    // ---- next-rank values for both quantiles in ONE pass --------------------
    float clo = 0.f, chi = 0.f;
    unsigned int mlo = 0xFFFFFFFFu, mhi = 0xFFFFFFFFu;
    for (int i = tid; i < NEL; i += T) {
        unsigned int u = uv[i];
        if (u <= ulo0) clo += 1.f; else mlo = min(mlo, u);
        if (u <= uhi0) chi += 1.f; else mhi = min(mhi, u);
    }
    float cleL = blockSum1024(clo, sbuf, tid);
    float cleH = blockSum1024(chi, sbuf, tid);
    unsigned int mgtL = blockMin1024(mlo, (unsigned int*)sbuf, tid);
    unsigned int mgtH = blockMin1024(mhi, (unsigned int*)sbuf, tid);
    unsigned int ulo1 = (cleL >= (float)(ilo + 2)) ? ulo0 : mgtL;
    unsigned int uhi1 = (cleH >= (float)(ihi + 2)) ? uhi0 : mgtH;

    float vlo0 = key_to_float(ulo0), vlo1 = key_to_float(ulo1);
    float vhi0 = key_to_float(uhi0), vhi1 = key_to_float(uhi1);
    float qlo = vlo0 + flo * (vlo1 - vlo0);
    float qhi = vhi0 + fhi * (vhi1 - vhi0);

    // ---- fused mask pass: cnt, sum, sumsq in one sweep -----------------------
    float lc = 0.f, ls = 0.f, lq = 0.f;
    for (int i = tid; i < NEL; i += T) {
        float v = key_to_float(uv[i]);
        if (v < qlo || v > qhi) { lc += 1.f; ls += v; lq = fmaf(v, v, lq); }
    }
    float cnt = blockSum1024(lc, sbuf, tid);
    float sum = blockSum1024(ls, sbuf, tid);
    float ssq = blockSum1024(lq, sbuf, tid);

    if (cnt < 0.5f) {
        // fallback: full-array moments
        float la = 0.f, lb = 0.f;
        for (int i = tid; i < NEL; i += T) {
            float v = key_to_float(uv[i]);
            la += v; lb = fmaf(v, v, lb);
        }
        float sumA = blockSum1024(la, sbuf, tid);
        float ssqA = blockSum1024(lb, sbuf, tid);
        float muA  = sumA / (float)NEL;
        float sdA  = sqrtf((ssqA - sumA * muA) / (float)(NEL - 1));
        lc = 0.f; ls = 0.f; lq = 0.f;
        for (int i = tid; i < NEL; i += T) {
            float v = key_to_float(uv[i]);
            if (fabsf(v - muA) > sdA) { lc += 1.f; ls += v; lq = fmaf(v, v, lq); }
        }
        cnt = blockSum1024(lc, sbuf, tid);
        sum = blockSum1024(ls, sbuf, tid);
        ssq = blockSum1024(lq, sbuf, tid);
        if (cnt < 0.5f) { cnt = (float)NEL; sum = sumA; ssq = ssqA; }
    }

    float ssd = ssq - sum * (sum / cnt);

    // ---- publish sigma; last block to finish computes the final output ------
    if (tid == 0) {
        g_sigma[arr] = sqrtf(ssd / (cnt - 1.0f));
        __threadfence();
        int done = atomicAdd(&g_done, 1);
        if (done == NARR - 1) {
            float acc = 0.f;
#pragma unroll
            for (int b = 0; b < NB; b++)
                acc += fmaxf(g_sigma[2 * b], g_sigma[2 * b + 1]);
            out[0] = acc * (1.0f / (float)NB);
            g_done = 0;           // reset for next graph replay
        }
    }
}

// ---------------------------------------------------------------------------
extern "C" void kernel_launch(void* const* d_in, const int* in_sizes, int n_in,
                              void* d_out, int out_size)
{
    const float* x = (const float*)d_in[0];
    const float* y = (const float*)d_in[1];
    float* out = (float*)d_out;
    (void)in_sizes; (void)n_in; (void)out_size;

    build_grid_kernel<<<NARR, 1024>>>(x, y);

    dim3 gridQ(NPTS / 256, NARR);
    nn_grid_kernel<<<gridQ, 256>>>();

    cudaFuncSetAttribute(robust_std_kernel,
                         cudaFuncAttributeMaxDynamicSharedMemorySize,
                         NEL * (int)sizeof(unsigned int));
    robust_std_kernel<<<NARR, 1024, NEL * sizeof(unsigned int)>>>(out);
}